// round 1
// baseline (speedup 1.0000x reference)
#include <cuda_runtime.h>
#include <cuda_bf16.h>
#include <cstdint>

#define BDIM 32
#define TDIM 512
#define HID  1024
#define NH   16
#define HD   64
#define BT   (BDIM * TDIM)   // 16384

// ---------------- scratch (device globals: allocation-free) ----------------
__device__ float g_Q[(size_t)BT * HID];
__device__ float g_K[(size_t)BT * HID];
__device__ float g_V[(size_t)BT * HID];
__device__ float g_C[(size_t)BT * HID];   // attention context
__device__ float g_O[(size_t)BT * HID];   // post output-proj

// ---------------------------------------------------------------------------
// GEMM: C[M=16384, N=1024] = A @ W^T + bias
//   LAYOUT_XT = true : A[m,k] = x[b*HID*T + k*T + t]  (m = b*T + t)  -- fused transpose
//   LAYOUT_XT = false: A[m,k] = A[m*1024 + k]         (row-major)
// Tile 128x128, BK=8, 256 threads, 8x8 per-thread microtile.
// ---------------------------------------------------------------------------
template <bool LAYOUT_XT>
__global__ void __launch_bounds__(256)
gemm_bias_kernel(const float* __restrict__ A, const float* __restrict__ W,
                 const float* __restrict__ bias, float* __restrict__ C)
{
    __shared__ float As[8][129];
    __shared__ float Ws[8][129];

    const int m0 = blockIdx.y * 128;
    const int n0 = blockIdx.x * 128;
    const int tid = threadIdx.x;
    const int ty = tid >> 4;      // 0..15
    const int tx = tid & 15;      // 0..15

    float acc[8][8];
#pragma unroll
    for (int i = 0; i < 8; ++i)
#pragma unroll
        for (int j = 0; j < 8; ++j) acc[i][j] = 0.f;

    // XT addressing precompute (tile never crosses batch: 128 | 512)
    const int b  = m0 >> 9;
    const int t0 = m0 & 511;
    const float* Xb = A + (size_t)b * HID * TDIM;

    // loader roles
    const int ml = tid & 127;            // XT: row within tile
    const int kb = (tid >> 7) * 4;       // XT: k sub-block {0,4}
    const int kl = tid & 7;              // RM: k within tile
    const int nl = tid >> 3;             // RM/W: row base (0..31)

    for (int k0 = 0; k0 < HID; k0 += 8) {
        if (LAYOUT_XT) {
#pragma unroll
            for (int j = 0; j < 4; ++j) {
                const int k = kb + j;
                As[k][ml] = Xb[(size_t)(k0 + k) * TDIM + t0 + ml];
            }
        } else {
#pragma unroll
            for (int j = 0; j < 4; ++j) {
                const int m = nl + j * 32;
                As[kl][m] = A[(size_t)(m0 + m) * HID + k0 + kl];
            }
        }
#pragma unroll
        for (int j = 0; j < 4; ++j) {
            const int n = nl + j * 32;
            Ws[kl][n] = W[(size_t)(n0 + n) * HID + k0 + kl];
        }
        __syncthreads();

#pragma unroll
        for (int k = 0; k < 8; ++k) {
            float a[8], w[8];
#pragma unroll
            for (int i = 0; i < 8; ++i) a[i] = As[k][ty * 8 + i];
#pragma unroll
            for (int j = 0; j < 8; ++j) w[j] = Ws[k][tx * 8 + j];
#pragma unroll
            for (int i = 0; i < 8; ++i)
#pragma unroll
                for (int j = 0; j < 8; ++j) acc[i][j] += a[i] * w[j];
        }
        __syncthreads();
    }

#pragma unroll
    for (int i = 0; i < 8; ++i) {
        const int m = m0 + ty * 8 + i;
#pragma unroll
        for (int j = 0; j < 8; ++j) {
            const int n = n0 + tx * 8 + j;
            C[(size_t)m * HID + n] = acc[i][j] + bias[n];
        }
    }
}

// ---------------------------------------------------------------------------
// Attention: per (b, head, q-tile of 64). 64x64 K/V tiles.
// Reference semantics: s = qk/8; masked -> -50; clip [-50,50]; softmax.
// Clipping bounds exp(s) within fp32 range => single pass, no running max.
// smem: Qs[64][65], Ks[64][65] (reused as P), Vs[64][65], den[64], msk[64]
// ---------------------------------------------------------------------------
#define ATTN_SMEM_FLOATS (3 * 64 * 65 + 64 + 64)
#define ATTN_SMEM_BYTES  (ATTN_SMEM_FLOATS * 4)

__global__ void __launch_bounds__(256)
attn_kernel(const float* __restrict__ Q, const float* __restrict__ K,
            const float* __restrict__ V, const int* __restrict__ mask,
            float* __restrict__ CTX)
{
    extern __shared__ float sm[];
    float (*Qs)[65] = (float (*)[65])sm;
    float (*Ks)[65] = (float (*)[65])(sm + 64 * 65);
    float (*Vs)[65] = (float (*)[65])(sm + 2 * 64 * 65);
    float* den = sm + 3 * 64 * 65;
    int*   msk = (int*)(sm + 3 * 64 * 65 + 64);

    const int qt = blockIdx.x;   // 0..7
    const int h  = blockIdx.y;   // 0..15
    const int b  = blockIdx.z;   // 0..31
    const int tid = threadIdx.x;
    const int ty = tid >> 4, tx = tid & 15;

    const size_t base = ((size_t)b * TDIM) * HID + h * HD;  // + row*HID + d
    const int q0 = qt * 64;

    // load Q tile (coalesced over d)
#pragma unroll
    for (int p = 0; p < 16; ++p) {
        const int idx = p * 256 + tid;
        const int q = idx >> 6, d = idx & 63;
        Qs[q][d] = Q[base + (size_t)(q0 + q) * HID + d];
    }
    if (tid < 64) den[tid] = 0.f;

    float acc[4][4];
#pragma unroll
    for (int i = 0; i < 4; ++i)
#pragma unroll
        for (int j = 0; j < 4; ++j) acc[i][j] = 0.f;

    for (int k0 = 0; k0 < TDIM; k0 += 64) {
        __syncthreads();   // previous iter done with Ks/Vs
#pragma unroll
        for (int p = 0; p < 16; ++p) {
            const int idx = p * 256 + tid;
            const int r = idx >> 6, d = idx & 63;
            Ks[r][d] = K[base + (size_t)(k0 + r) * HID + d];
            Vs[r][d] = V[base + (size_t)(k0 + r) * HID + d];
        }
        if (tid < 64) msk[tid] = mask[b * TDIM + k0 + tid];
        __syncthreads();

        // S = Q K^T  (4x4 per thread)
        float s[4][4];
#pragma unroll
        for (int i = 0; i < 4; ++i)
#pragma unroll
            for (int j = 0; j < 4; ++j) s[i][j] = 0.f;

        for (int d = 0; d < 64; ++d) {
            float qv[4], kv[4];
#pragma unroll
            for (int i = 0; i < 4; ++i) qv[i] = Qs[ty * 4 + i][d];
#pragma unroll
            for (int j = 0; j < 4; ++j) kv[j] = Ks[tx * 4 + j][d];
#pragma unroll
            for (int i = 0; i < 4; ++i)
#pragma unroll
                for (int j = 0; j < 4; ++j) s[i][j] += qv[i] * kv[j];
        }
        __syncthreads();   // everyone done reading Ks

        // P = exp(mask/clip(S/8))  -> stored into Ks
#pragma unroll
        for (int i = 0; i < 4; ++i)
#pragma unroll
            for (int j = 0; j < 4; ++j) {
                float v = s[i][j] * 0.125f;
                v = (msk[tx * 4 + j] == 0) ? -50.f
                                           : fminf(fmaxf(v, -50.f), 50.f);
                Ks[ty * 4 + i][tx * 4 + j] = __expf(v);
            }
        __syncthreads();

        // row sums (denominator)
        if (tid < 64) {
            float r = 0.f;
#pragma unroll 8
            for (int k = 0; k < 64; ++k) r += Ks[tid][k];
            den[tid] += r;
        }

        // acc += P @ V
        for (int k = 0; k < 64; ++k) {
            float pv[4], vv[4];
#pragma unroll
            for (int i = 0; i < 4; ++i) pv[i] = Ks[ty * 4 + i][k];
#pragma unroll
            for (int j = 0; j < 4; ++j) vv[j] = Vs[k][tx * 4 + j];
#pragma unroll
            for (int i = 0; i < 4; ++i)
#pragma unroll
                for (int j = 0; j < 4; ++j) acc[i][j] += pv[i] * vv[j];
        }
    }
    __syncthreads();   // den visible

#pragma unroll
    for (int i = 0; i < 4; ++i) {
        const float inv = 1.f / den[ty * 4 + i];
        const size_t row = base + (size_t)(q0 + ty * 4 + i) * HID;
#pragma unroll
        for (int j = 0; j < 4; ++j)
            CTX[row + tx * 4 + j] = acc[i][j] * inv;
    }
}

// ---------------------------------------------------------------------------
// out[b, n] = max_t O[(b*T + t)*HID + n]
// ---------------------------------------------------------------------------
__global__ void __launch_bounds__(256)
maxreduce_kernel(const float* __restrict__ O, float* __restrict__ out)
{
    const int b = blockIdx.x;
    const int n = blockIdx.y * 256 + threadIdx.x;
    const float* p = O + (size_t)b * TDIM * HID + n;
    float m = -3.402823466e38f;
#pragma unroll 8
    for (int t = 0; t < TDIM; ++t) m = fmaxf(m, p[(size_t)t * HID]);
    out[b * HID + n] = m;
}

// ---------------------------------------------------------------------------
extern "C" void kernel_launch(void* const* d_in, const int* in_sizes, int n_in,
                              void* d_out, int out_size)
{
    const float* x    = (const float*)d_in[0];
    const int*   mask = (const int*)d_in[1];
    const float* Wq   = (const float*)d_in[2];
    const float* bq   = (const float*)d_in[3];
    const float* Wk   = (const float*)d_in[4];
    const float* bk   = (const float*)d_in[5];
    const float* Wv   = (const float*)d_in[6];
    const float* bv   = (const float*)d_in[7];
    const float* Wo   = (const float*)d_in[8];
    const float* bo   = (const float*)d_in[9];
    float* out = (float*)d_out;

    float *Q, *K, *V, *C, *O;
    cudaGetSymbolAddress((void**)&Q, g_Q);
    cudaGetSymbolAddress((void**)&K, g_K);
    cudaGetSymbolAddress((void**)&V, g_V);
    cudaGetSymbolAddress((void**)&C, g_C);
    cudaGetSymbolAddress((void**)&O, g_O);

    cudaFuncSetAttribute(attn_kernel,
                         cudaFuncAttributeMaxDynamicSharedMemorySize,
                         ATTN_SMEM_BYTES);

    dim3 gg(HID / 128, BT / 128);   // (8, 128)

    gemm_bias_kernel<true><<<gg, 256>>>(x, Wq, bq, Q);
    gemm_bias_kernel<true><<<gg, 256>>>(x, Wk, bk, K);
    gemm_bias_kernel<true><<<gg, 256>>>(x, Wv, bv, V);

    attn_kernel<<<dim3(TDIM / 64, NH, BDIM), 256, ATTN_SMEM_BYTES>>>(Q, K, V, mask, C);

    gemm_bias_kernel<false><<<gg, 256>>>(C, Wo, bo, O);

    maxreduce_kernel<<<dim3(BDIM, HID / 256), 256>>>(O, out);
}

// round 3
// speedup vs baseline: 2.3645x; 2.3645x over previous
#include <cuda_runtime.h>
#include <cuda_bf16.h>
#include <cstdint>

#define BDIM 32
#define TDIM 512
#define HID  1024
#define NH   16
#define HD   64
#define BT   (BDIM * TDIM)   // 16384

// ------------------------- scratch (device globals) -------------------------
__device__ float         g_Q  [(size_t)BT * HID];
__device__ float         g_K  [(size_t)BT * HID];
__device__ float         g_V  [(size_t)BT * HID];
__device__ float         g_CTX[(size_t)BT * HID];
__device__ float         g_O  [(size_t)BT * HID];
__device__ __nv_bfloat16 g_xhi[(size_t)BT * HID];
__device__ __nv_bfloat16 g_xlo[(size_t)BT * HID];
__device__ __nv_bfloat16 g_chi[(size_t)BT * HID];
__device__ __nv_bfloat16 g_clo[(size_t)BT * HID];
__device__ __nv_bfloat16 g_whi[(size_t)4 * HID * HID];
__device__ __nv_bfloat16 g_wlo[(size_t)4 * HID * HID];

// ------------------------------ PTX helpers --------------------------------
__device__ __forceinline__ uint32_t smem_u32(const void* p) {
    uint32_t a;
    asm("{ .reg .u64 t; cvta.to.shared.u64 t, %1; cvt.u32.u64 %0, t; }" : "=r"(a) : "l"(p));
    return a;
}
__device__ __forceinline__ void ldm_x4(uint32_t* r, uint32_t addr) {
    asm volatile("ldmatrix.sync.aligned.m8n8.x4.shared.b16 {%0,%1,%2,%3}, [%4];"
                 : "=r"(r[0]), "=r"(r[1]), "=r"(r[2]), "=r"(r[3]) : "r"(addr));
}
__device__ __forceinline__ void mma16816(float* c, const uint32_t* a, const uint32_t* b) {
    asm volatile("mma.sync.aligned.m16n8k16.row.col.f32.bf16.bf16.f32 "
                 "{%0,%1,%2,%3}, {%4,%5,%6,%7}, {%8,%9}, {%0,%1,%2,%3};"
                 : "+f"(c[0]), "+f"(c[1]), "+f"(c[2]), "+f"(c[3])
                 : "r"(a[0]), "r"(a[1]), "r"(a[2]), "r"(a[3]), "r"(b[0]), "r"(b[1]));
}
#define CP_ASYNC16(saddr, gptr) \
    asm volatile("cp.async.cg.shared.global [%0], [%1], 16;" :: "r"(saddr), "l"(gptr))
#define CP_COMMIT() asm volatile("cp.async.commit_group;" ::: "memory")
#define CP_WAIT0()  asm volatile("cp.async.wait_group 0;" ::: "memory")

// ---------------------------------------------------------------------------
// mma.sync GEMM: C[16384,1024] = (Ah+Al) @ (Wh+Wl)^T + bias   (fp32 acc)
// Block tile 128x128, BK=32, 8 warps (2x4), warp tile 64x32.
// smem: 2 stages x 4 operands x [128 rows x pitch-40 bf16]  (conflict-free ldmatrix)
// ---------------------------------------------------------------------------
#define BK      32
#define NCHUNK  (HID / BK)          // 32
#define PITCH   40                  // bf16 elems per smem row (80B)
#define TILE_B  (128 * PITCH * 2)   // 10240 bytes
#define STAGE_B (4 * TILE_B)        // 40960
#define GEMM_SMEM_BYTES (2 * STAGE_B)

__global__ void __launch_bounds__(256)
gemm_mma_kernel(const __nv_bfloat16* __restrict__ Ah, const __nv_bfloat16* __restrict__ Al,
                const __nv_bfloat16* __restrict__ Wh, const __nv_bfloat16* __restrict__ Wl,
                const float* __restrict__ bias, float* __restrict__ C)
{
    extern __shared__ __align__(128) char smem[];
    const uint32_t sbase = smem_u32(smem);
    const int tid  = threadIdx.x;
    const int wid  = tid >> 5, lane = tid & 31;
    const int wm   = wid >> 2;          // 0..1   (64 rows)
    const int wn   = wid & 3;           // 0..3   (32 cols)
    const int m0   = blockIdx.y * 128;
    const int n0   = blockIdx.x * 128;

    float acc[4][4][4];
#pragma unroll
    for (int i = 0; i < 4; ++i)
#pragma unroll
        for (int j = 0; j < 4; ++j)
#pragma unroll
            for (int e = 0; e < 4; ++e) acc[i][j][e] = 0.f;

    // ---- async tile copy: chunk c -> stage s ----
    auto issue_copy = [&](int c, int s) {
        const int k0 = c * BK;
        const uint32_t sb = sbase + s * STAGE_B;
#pragma unroll
        for (int op = 0; op < 4; ++op) {
            const __nv_bfloat16* src = (op == 0) ? Ah : (op == 1) ? Al : (op == 2) ? Wh : Wl;
            const int rbase = (op < 2) ? m0 : n0;
#pragma unroll
            for (int i = 0; i < 2; ++i) {
                const int u   = i * 256 + tid;      // 512 uint4 per operand
                const int row = u >> 2;
                const int cv  = u & 3;
                const void* g = src + (size_t)(rbase + row) * HID + k0 + cv * 8;
                const uint32_t sa = sb + op * TILE_B + row * (PITCH * 2) + cv * 16;
                CP_ASYNC16(sa, g);
            }
        }
        CP_COMMIT();
    };

    // ---- per-stage compute ----
    auto compute = [&](int s) {
        const uint32_t sb  = sbase + s * STAGE_B;
        const uint32_t aAh = sb;
        const uint32_t aAl = sb + TILE_B;
        const uint32_t aWh = sb + 2 * TILE_B;
        const uint32_t aWl = sb + 3 * TILE_B;

        // precomputed lane offsets (elements)
        const int arow = wm * 64 + (lane & 15);
        const int acol = (lane >> 4) * 8;
        const int brow = wn * 32 + (lane & 7) + (lane >> 4) * 8;
        const int bcol = ((lane >> 3) & 1) * 8;

#pragma unroll
        for (int ks = 0; ks < 2; ++ks) {
            uint32_t ah[4][4], al[4][4];
#pragma unroll
            for (int i = 0; i < 4; ++i) {
                const uint32_t off = (arow + i * 16) * (PITCH * 2) + (ks * 16 + acol) * 2;
                ldm_x4(ah[i], aAh + off);
                ldm_x4(al[i], aAl + off);
            }
            uint32_t bh[8], bl[8];
#pragma unroll
            for (int jj = 0; jj < 2; ++jj) {
                const uint32_t off = (brow + jj * 16) * (PITCH * 2) + (ks * 16 + bcol) * 2;
                ldm_x4(&bh[jj * 4], aWh + off);
                ldm_x4(&bl[jj * 4], aWl + off);
            }
#pragma unroll
            for (int i = 0; i < 4; ++i)
#pragma unroll
                for (int j = 0; j < 4; ++j) {
                    const int bi = (j >> 1) * 4 + (j & 1) * 2;
                    mma16816(acc[i][j], ah[i], &bh[bi]);   // hi*hi
                    mma16816(acc[i][j], ah[i], &bl[bi]);   // hi*lo
                    mma16816(acc[i][j], al[i], &bh[bi]);   // lo*hi
                }
        }
    };

    issue_copy(0, 0);
#pragma unroll 1
    for (int c = 0; c < NCHUNK; ++c) {
        CP_WAIT0();
        __syncthreads();
        if (c + 1 < NCHUNK) issue_copy(c + 1, (c + 1) & 1);
        compute(c & 1);
        __syncthreads();
    }

    // ---- epilogue ----
#pragma unroll
    for (int i = 0; i < 4; ++i) {
        const int r0 = m0 + wm * 64 + i * 16 + (lane >> 2);
#pragma unroll
        for (int j = 0; j < 4; ++j) {
            const int col = n0 + wn * 32 + j * 8 + (lane & 3) * 2;
            const float bx = bias[col], by = bias[col + 1];
            float2 v0 = { acc[i][j][0] + bx, acc[i][j][1] + by };
            float2 v1 = { acc[i][j][2] + bx, acc[i][j][3] + by };
            *(float2*)(C + (size_t)r0 * HID + col)       = v0;
            *(float2*)(C + (size_t)(r0 + 8) * HID + col) = v1;
        }
    }
}

// ---------------------------------------------------------------------------
// x [B, HID, T] fp32 -> transpose to [BT, HID] + split into bf16 hi/lo
// ---------------------------------------------------------------------------
__global__ void __launch_bounds__(256)
xpose_split_kernel(const float* __restrict__ x,
                   __nv_bfloat16* __restrict__ hi, __nv_bfloat16* __restrict__ lo)
{
    __shared__ float s[32][33];
    const int b = blockIdx.z, k0 = blockIdx.y * 32, t0 = blockIdx.x * 32;
    const int tx = threadIdx.x & 31, ty = threadIdx.x >> 5;   // 32 x 8
    const float* src = x + ((size_t)b * HID + k0) * TDIM + t0;
#pragma unroll
    for (int i = 0; i < 4; ++i)
        s[ty + 8 * i][tx] = src[(size_t)(ty + 8 * i) * TDIM + tx];
    __syncthreads();
#pragma unroll
    for (int i = 0; i < 4; ++i) {
        const int t = ty + 8 * i;
        const float v = s[tx][t];
        const __nv_bfloat16 h = __float2bfloat16_rn(v);
        const __nv_bfloat16 l = __float2bfloat16_rn(v - __bfloat162float(h));
        const size_t o = (size_t)(b * TDIM + t0 + t) * HID + k0 + tx;
        hi[o] = h;
        lo[o] = l;
    }
}

// elementwise fp32 -> bf16 hi/lo split (row-major, vectorized x4)
__global__ void __launch_bounds__(256)
split_kernel(const float* __restrict__ src,
             __nv_bfloat16* __restrict__ hi, __nv_bfloat16* __restrict__ lo, int n4)
{
    const int i = blockIdx.x * 256 + threadIdx.x;
    if (i >= n4) return;
    const float4 v = ((const float4*)src)[i];
    float hx = __bfloat162float(__float2bfloat16_rn(v.x));
    float hy = __bfloat162float(__float2bfloat16_rn(v.y));
    float hz = __bfloat162float(__float2bfloat16_rn(v.z));
    float hw = __bfloat162float(__float2bfloat16_rn(v.w));
    __nv_bfloat162 h0 = __floats2bfloat162_rn(v.x, v.y);
    __nv_bfloat162 h1 = __floats2bfloat162_rn(v.z, v.w);
    __nv_bfloat162 l0 = __floats2bfloat162_rn(v.x - hx, v.y - hy);
    __nv_bfloat162 l1 = __floats2bfloat162_rn(v.z - hz, v.w - hw);
    uint2 hp, lp;
    hp.x = *(uint32_t*)&h0; hp.y = *(uint32_t*)&h1;
    lp.x = *(uint32_t*)&l0; lp.y = *(uint32_t*)&l1;
    ((uint2*)hi)[i] = hp;
    ((uint2*)lo)[i] = lp;
}

// ---------------------------------------------------------------------------
// Attention: per (b, head, 64-q tile), 64x64 KV tiles, fp32 CUDA cores.
// Clip to [-50,50] before softmax => single-pass sum-exp is exact.
// ---------------------------------------------------------------------------
#define ATTN_SMEM_FLOATS (3 * 64 * 65 + 64 + 64)
#define ATTN_SMEM_BYTES  (ATTN_SMEM_FLOATS * 4)

__global__ void __launch_bounds__(256)
attn_kernel(const float* __restrict__ Q, const float* __restrict__ K,
            const float* __restrict__ V, const int* __restrict__ mask,
            float* __restrict__ CTX)
{
    extern __shared__ float sm[];
    float (*Qs)[65] = (float (*)[65])sm;
    float (*Ks)[65] = (float (*)[65])(sm + 64 * 65);
    float (*Vs)[65] = (float (*)[65])(sm + 2 * 64 * 65);
    float* den = sm + 3 * 64 * 65;
    int*   msk = (int*)(sm + 3 * 64 * 65 + 64);

    const int qt = blockIdx.x, h = blockIdx.y, b = blockIdx.z;
    const int tid = threadIdx.x;
    const int ty = tid >> 4, tx = tid & 15;
    const size_t base = ((size_t)b * TDIM) * HID + h * HD;
    const int q0 = qt * 64;

#pragma unroll
    for (int p = 0; p < 16; ++p) {
        const int idx = p * 256 + tid;
        const int q = idx >> 6, d = idx & 63;
        Qs[q][d] = Q[base + (size_t)(q0 + q) * HID + d];
    }
    if (tid < 64) den[tid] = 0.f;

    float acc[4][4];
#pragma unroll
    for (int i = 0; i < 4; ++i)
#pragma unroll
        for (int j = 0; j < 4; ++j) acc[i][j] = 0.f;

    for (int k0 = 0; k0 < TDIM; k0 += 64) {
        __syncthreads();
#pragma unroll
        for (int p = 0; p < 16; ++p) {
            const int idx = p * 256 + tid;
            const int r = idx >> 6, d = idx & 63;
            Ks[r][d] = K[base + (size_t)(k0 + r) * HID + d];
            Vs[r][d] = V[base + (size_t)(k0 + r) * HID + d];
        }
        if (tid < 64) msk[tid] = mask[b * TDIM + k0 + tid];
        __syncthreads();

        float s[4][4];
#pragma unroll
        for (int i = 0; i < 4; ++i)
#pragma unroll
            for (int j = 0; j < 4; ++j) s[i][j] = 0.f;

        for (int d = 0; d < 64; ++d) {
            float qv[4], kv[4];
#pragma unroll
            for (int i = 0; i < 4; ++i) qv[i] = Qs[ty * 4 + i][d];
#pragma unroll
            for (int j = 0; j < 4; ++j) kv[j] = Ks[tx * 4 + j][d];
#pragma unroll
            for (int i = 0; i < 4; ++i)
#pragma unroll
                for (int j = 0; j < 4; ++j) s[i][j] += qv[i] * kv[j];
        }
        __syncthreads();

#pragma unroll
        for (int i = 0; i < 4; ++i)
#pragma unroll
            for (int j = 0; j < 4; ++j) {
                float v = s[i][j] * 0.125f;
                v = (msk[tx * 4 + j] == 0) ? -50.f : fminf(fmaxf(v, -50.f), 50.f);
                Ks[ty * 4 + i][tx * 4 + j] = __expf(v);
            }
        __syncthreads();

        if (tid < 64) {
            float r = 0.f;
#pragma unroll 8
            for (int k = 0; k < 64; ++k) r += Ks[tid][k];
            den[tid] += r;
        }

        for (int k = 0; k < 64; ++k) {
            float pv[4], vv[4];
#pragma unroll
            for (int i = 0; i < 4; ++i) pv[i] = Ks[ty * 4 + i][k];
#pragma unroll
            for (int j = 0; j < 4; ++j) vv[j] = Vs[k][tx * 4 + j];
#pragma unroll
            for (int i = 0; i < 4; ++i)
#pragma unroll
                for (int j = 0; j < 4; ++j) acc[i][j] += pv[i] * vv[j];
        }
    }
    __syncthreads();

#pragma unroll
    for (int i = 0; i < 4; ++i) {
        const float inv = 1.f / den[ty * 4 + i];
        const size_t row = base + (size_t)(q0 + ty * 4 + i) * HID;
#pragma unroll
        for (int j = 0; j < 4; ++j)
            CTX[row + tx * 4 + j] = acc[i][j] * inv;
    }
}

// ---------------------------------------------------------------------------
__global__ void __launch_bounds__(256)
maxreduce_kernel(const float* __restrict__ O, float* __restrict__ out)
{
    const int b = blockIdx.x;
    const int n = blockIdx.y * 256 + threadIdx.x;
    const float* p = O + (size_t)b * TDIM * HID + n;
    float m = -3.402823466e38f;
#pragma unroll 8
    for (int t = 0; t < TDIM; ++t) m = fmaxf(m, p[(size_t)t * HID]);
    out[b * HID + n] = m;
}

// ---------------------------------------------------------------------------
extern "C" void kernel_launch(void* const* d_in, const int* in_sizes, int n_in,
                              void* d_out, int out_size)
{
    const float* x    = (const float*)d_in[0];
    const int*   mask = (const int*)d_in[1];
    const float* W[4] = { (const float*)d_in[2], (const float*)d_in[4],
                          (const float*)d_in[6], (const float*)d_in[8] };   // q,k,v,o
    const float* bq   = (const float*)d_in[3];
    const float* bk   = (const float*)d_in[5];
    const float* bv   = (const float*)d_in[7];
    const float* bo   = (const float*)d_in[9];
    float* out = (float*)d_out;

    float *Q, *K, *V, *CTX, *O;
    __nv_bfloat16 *xhi, *xlo, *chi, *clo, *whi, *wlo;
    cudaGetSymbolAddress((void**)&Q,   g_Q);
    cudaGetSymbolAddress((void**)&K,   g_K);
    cudaGetSymbolAddress((void**)&V,   g_V);
    cudaGetSymbolAddress((void**)&CTX, g_CTX);
    cudaGetSymbolAddress((void**)&O,   g_O);
    cudaGetSymbolAddress((void**)&xhi, g_xhi);
    cudaGetSymbolAddress((void**)&xlo, g_xlo);
    cudaGetSymbolAddress((void**)&chi, g_chi);
    cudaGetSymbolAddress((void**)&clo, g_clo);
    cudaGetSymbolAddress((void**)&whi, g_whi);
    cudaGetSymbolAddress((void**)&wlo, g_wlo);

    cudaFuncSetAttribute(attn_kernel, cudaFuncAttributeMaxDynamicSharedMemorySize,
                         ATTN_SMEM_BYTES);
    cudaFuncSetAttribute(gemm_mma_kernel, cudaFuncAttributeMaxDynamicSharedMemorySize,
                         GEMM_SMEM_BYTES);

    // weight splits (4 x 1M elements)
    const int wn4 = HID * HID / 4;
    for (int i = 0; i < 4; ++i)
        split_kernel<<<(wn4 + 255) / 256, 256>>>(W[i], whi + (size_t)i * HID * HID,
                                                 wlo + (size_t)i * HID * HID, wn4);
    // x transpose + split
    xpose_split_kernel<<<dim3(TDIM / 32, HID / 32, BDIM), 256>>>(x, xhi, xlo);

    const dim3 gg(HID / 128, BT / 128);   // (8, 128)
    const size_t WSZ = (size_t)HID * HID;

    gemm_mma_kernel<<<gg, 256, GEMM_SMEM_BYTES>>>(xhi, xlo, whi + 0 * WSZ, wlo + 0 * WSZ, bq, Q);
    gemm_mma_kernel<<<gg, 256, GEMM_SMEM_BYTES>>>(xhi, xlo, whi + 1 * WSZ, wlo + 1 * WSZ, bk, K);
    gemm_mma_kernel<<<gg, 256, GEMM_SMEM_BYTES>>>(xhi, xlo, whi + 2 * WSZ, wlo + 2 * WSZ, bv, V);

    attn_kernel<<<dim3(TDIM / 64, NH, BDIM), 256, ATTN_SMEM_BYTES>>>(Q, K, V, mask, CTX);

    const int cn4 = BT * HID / 4;
    split_kernel<<<(cn4 + 255) / 256, 256>>>(CTX, chi, clo, cn4);

    gemm_mma_kernel<<<gg, 256, GEMM_SMEM_BYTES>>>(chi, clo, whi + 3 * WSZ, wlo + 3 * WSZ, bo, O);

    maxreduce_kernel<<<dim3(BDIM, HID / 256), 256>>>(O, out);
}

// round 4
// speedup vs baseline: 3.4925x; 1.4770x over previous
#include <cuda_runtime.h>
#include <cuda_bf16.h>
#include <cstdint>

#define BDIM 32
#define TDIM 512
#define HID  1024
#define NH   16
#define HD   64
#define BT   (BDIM * TDIM)   // 16384

// ------------------------- scratch (device globals) -------------------------
__device__ float         g_O  [(size_t)BT * HID];
__device__ __nv_bfloat16 g_xhi[(size_t)BT * HID];
__device__ __nv_bfloat16 g_xlo[(size_t)BT * HID];
__device__ __nv_bfloat16 g_qhi[(size_t)BT * HID];
__device__ __nv_bfloat16 g_qlo[(size_t)BT * HID];
__device__ __nv_bfloat16 g_khi[(size_t)BT * HID];
__device__ __nv_bfloat16 g_klo[(size_t)BT * HID];
__device__ __nv_bfloat16 g_vhi[(size_t)BT * HID];
__device__ __nv_bfloat16 g_vlo[(size_t)BT * HID];
__device__ __nv_bfloat16 g_chi[(size_t)BT * HID];
__device__ __nv_bfloat16 g_clo[(size_t)BT * HID];
__device__ __nv_bfloat16 g_whi[(size_t)4 * HID * HID];
__device__ __nv_bfloat16 g_wlo[(size_t)4 * HID * HID];

// ------------------------------ PTX helpers --------------------------------
__device__ __forceinline__ uint32_t smem_u32(const void* p) {
    uint32_t a;
    asm("{ .reg .u64 t; cvta.to.shared.u64 t, %1; cvt.u32.u64 %0, t; }" : "=r"(a) : "l"(p));
    return a;
}
__device__ __forceinline__ void ldm_x4(uint32_t* r, uint32_t addr) {
    asm volatile("ldmatrix.sync.aligned.m8n8.x4.shared.b16 {%0,%1,%2,%3}, [%4];"
                 : "=r"(r[0]), "=r"(r[1]), "=r"(r[2]), "=r"(r[3]) : "r"(addr));
}
__device__ __forceinline__ void ldm_x4_t(uint32_t* r, uint32_t addr) {
    asm volatile("ldmatrix.sync.aligned.m8n8.x4.trans.shared.b16 {%0,%1,%2,%3}, [%4];"
                 : "=r"(r[0]), "=r"(r[1]), "=r"(r[2]), "=r"(r[3]) : "r"(addr));
}
__device__ __forceinline__ void mma16816(float* c, const uint32_t* a, const uint32_t* b) {
    asm volatile("mma.sync.aligned.m16n8k16.row.col.f32.bf16.bf16.f32 "
                 "{%0,%1,%2,%3}, {%4,%5,%6,%7}, {%8,%9}, {%0,%1,%2,%3};"
                 : "+f"(c[0]), "+f"(c[1]), "+f"(c[2]), "+f"(c[3])
                 : "r"(a[0]), "r"(a[1]), "r"(a[2]), "r"(a[3]), "r"(b[0]), "r"(b[1]));
}
#define CP_ASYNC16(saddr, gptr) \
    asm volatile("cp.async.cg.shared.global [%0], [%1], 16;" :: "r"(saddr), "l"(gptr))
#define CP_COMMIT() asm volatile("cp.async.commit_group;" ::: "memory")
#define CP_WAIT0()  asm volatile("cp.async.wait_group 0;" ::: "memory")

__device__ __forceinline__ uint32_t pack_hi(float a, float b) {
    __nv_bfloat162 h = __floats2bfloat162_rn(a, b);
    return *(uint32_t*)&h;
}
// pack residuals: lo = v - float(bf16(v))
__device__ __forceinline__ uint32_t pack_lo(float a, float b) {
    float ra = a - __bfloat162float(__float2bfloat16_rn(a));
    float rb = b - __bfloat162float(__float2bfloat16_rn(b));
    __nv_bfloat162 l = __floats2bfloat162_rn(ra, rb);
    return *(uint32_t*)&l;
}

// ---------------------------------------------------------------------------
// mma.sync GEMM: C[16384,1024] = (Ah+Al) @ (Wh+Wl)^T + bias   (fp32 acc)
// Block tile 128x128, BK=32, 8 warps (2x4), warp tile 64x32.
// SPLIT_OUT=true: write bf16 hi/lo pair instead of fp32.
// ---------------------------------------------------------------------------
#define BK      32
#define NCHUNK  (HID / BK)          // 32
#define PITCH   40                  // bf16 elems per smem row (80B)
#define TILE_B  (128 * PITCH * 2)   // 10240 bytes
#define STAGE_B (4 * TILE_B)        // 40960
#define GEMM_SMEM_BYTES (2 * STAGE_B)

template <bool SPLIT_OUT>
__global__ void __launch_bounds__(256)
gemm_mma_kernel(const __nv_bfloat16* __restrict__ Ah, const __nv_bfloat16* __restrict__ Al,
                const __nv_bfloat16* __restrict__ Wh, const __nv_bfloat16* __restrict__ Wl,
                const float* __restrict__ bias, float* __restrict__ C,
                __nv_bfloat16* __restrict__ Chi, __nv_bfloat16* __restrict__ Clo)
{
    extern __shared__ __align__(128) char smem[];
    const uint32_t sbase = smem_u32(smem);
    const int tid  = threadIdx.x;
    const int wid  = tid >> 5, lane = tid & 31;
    const int wm   = wid >> 2;
    const int wn   = wid & 3;
    const int m0   = blockIdx.y * 128;
    const int n0   = blockIdx.x * 128;

    float acc[4][4][4];
#pragma unroll
    for (int i = 0; i < 4; ++i)
#pragma unroll
        for (int j = 0; j < 4; ++j)
#pragma unroll
            for (int e = 0; e < 4; ++e) acc[i][j][e] = 0.f;

    auto issue_copy = [&](int c, int s) {
        const int k0 = c * BK;
        const uint32_t sb = sbase + s * STAGE_B;
#pragma unroll
        for (int op = 0; op < 4; ++op) {
            const __nv_bfloat16* src = (op == 0) ? Ah : (op == 1) ? Al : (op == 2) ? Wh : Wl;
            const int rbase = (op < 2) ? m0 : n0;
#pragma unroll
            for (int i = 0; i < 2; ++i) {
                const int u   = i * 256 + tid;
                const int row = u >> 2;
                const int cv  = u & 3;
                const void* g = src + (size_t)(rbase + row) * HID + k0 + cv * 8;
                const uint32_t sa = sb + op * TILE_B + row * (PITCH * 2) + cv * 16;
                CP_ASYNC16(sa, g);
            }
        }
        CP_COMMIT();
    };

    auto compute = [&](int s) {
        const uint32_t sb  = sbase + s * STAGE_B;
        const uint32_t aAh = sb;
        const uint32_t aAl = sb + TILE_B;
        const uint32_t aWh = sb + 2 * TILE_B;
        const uint32_t aWl = sb + 3 * TILE_B;

        const int arow = wm * 64 + (lane & 15);
        const int acol = (lane >> 4) * 8;
        const int brow = wn * 32 + (lane & 7) + (lane >> 4) * 8;
        const int bcol = ((lane >> 3) & 1) * 8;

#pragma unroll
        for (int ks = 0; ks < 2; ++ks) {
            uint32_t ah[4][4], al[4][4];
#pragma unroll
            for (int i = 0; i < 4; ++i) {
                const uint32_t off = (arow + i * 16) * (PITCH * 2) + (ks * 16 + acol) * 2;
                ldm_x4(ah[i], aAh + off);
                ldm_x4(al[i], aAl + off);
            }
            uint32_t bh[8], bl[8];
#pragma unroll
            for (int jj = 0; jj < 2; ++jj) {
                const uint32_t off = (brow + jj * 16) * (PITCH * 2) + (ks * 16 + bcol) * 2;
                ldm_x4(&bh[jj * 4], aWh + off);
                ldm_x4(&bl[jj * 4], aWl + off);
            }
#pragma unroll
            for (int i = 0; i < 4; ++i)
#pragma unroll
                for (int j = 0; j < 4; ++j) {
                    const int bi = (j >> 1) * 4 + (j & 1) * 2;
                    mma16816(acc[i][j], ah[i], &bh[bi]);
                    mma16816(acc[i][j], ah[i], &bl[bi]);
                    mma16816(acc[i][j], al[i], &bh[bi]);
                }
        }
    };

    issue_copy(0, 0);
#pragma unroll 1
    for (int c = 0; c < NCHUNK; ++c) {
        CP_WAIT0();
        __syncthreads();
        if (c + 1 < NCHUNK) issue_copy(c + 1, (c + 1) & 1);
        compute(c & 1);
        __syncthreads();
    }

#pragma unroll
    for (int i = 0; i < 4; ++i) {
        const int r0 = m0 + wm * 64 + i * 16 + (lane >> 2);
#pragma unroll
        for (int j = 0; j < 4; ++j) {
            const int col = n0 + wn * 32 + j * 8 + (lane & 3) * 2;
            const float bx = bias[col], by = bias[col + 1];
            const float v0 = acc[i][j][0] + bx, v1 = acc[i][j][1] + by;
            const float v2 = acc[i][j][2] + bx, v3 = acc[i][j][3] + by;
            if (SPLIT_OUT) {
                const size_t o0 = (size_t)r0 * HID + col;
                const size_t o1 = (size_t)(r0 + 8) * HID + col;
                *(uint32_t*)(Chi + o0) = pack_hi(v0, v1);
                *(uint32_t*)(Clo + o0) = pack_lo(v0, v1);
                *(uint32_t*)(Chi + o1) = pack_hi(v2, v3);
                *(uint32_t*)(Clo + o1) = pack_lo(v2, v3);
            } else {
                float2 a0 = { v0, v1 }, a1 = { v2, v3 };
                *(float2*)(C + (size_t)r0 * HID + col)       = a0;
                *(float2*)(C + (size_t)(r0 + 8) * HID + col) = a1;
            }
        }
    }
}

// ---------------------------------------------------------------------------
// Tensor-core attention: block = (b, h, 128 q-rows). KV chunks of 64 keys.
// S = Qh*Kh + Qh*Kl + Ql*Kh; softmax in regs (clip => single pass);
// PV = Ph*Vh + Ph*Vl + Pl*Vh. Writes CTX as bf16 hi/lo.
// ---------------------------------------------------------------------------
#define APITCH 72                       // bf16 elems/row (144B)
#define AP2    (APITCH * 2)
#define SM_QH  0
#define SM_QL  (128 * AP2)              // 18432
#define SM_KH  (2 * 128 * AP2)          // 36864
#define SM_KL  (SM_KH + 64 * AP2)
#define SM_VH  (SM_KH + 2 * 64 * AP2)
#define SM_VL  (SM_KH + 3 * 64 * AP2)
#define SM_MSK (SM_KH + 4 * 64 * AP2)   // 73728
#define ATTN_SMEM_BYTES (SM_MSK + 64 * 4)

__global__ void __launch_bounds__(256)
attn_mma_kernel(const __nv_bfloat16* __restrict__ Qh, const __nv_bfloat16* __restrict__ Ql,
                const __nv_bfloat16* __restrict__ Kh, const __nv_bfloat16* __restrict__ Kl,
                const __nv_bfloat16* __restrict__ Vh, const __nv_bfloat16* __restrict__ Vl,
                const int* __restrict__ mask,
                __nv_bfloat16* __restrict__ Chi, __nv_bfloat16* __restrict__ Clo)
{
    extern __shared__ __align__(128) char smem[];
    const uint32_t sb = smem_u32(smem);
    float* msk01 = (float*)(smem + SM_MSK);

    const int tid  = threadIdx.x;
    const int wid  = tid >> 5, lane = tid & 31;
    const int q0   = blockIdx.x * 128;
    const int h    = blockIdx.y;
    const int b    = blockIdx.z;
    const size_t rowbase = (size_t)b * TDIM;   // token row = rowbase + t
    const int colbase = h * HD;

    // ---- load Q tile (128 x 64) hi/lo ----
    {
#pragma unroll
        for (int op = 0; op < 2; ++op) {
            const __nv_bfloat16* src = op ? Ql : Qh;
            const uint32_t so = sb + (op ? SM_QL : SM_QH);
#pragma unroll
            for (int i = 0; i < 4; ++i) {
                const int u = i * 256 + tid;
                const int r = u >> 3, cv = u & 7;
                const void* g = src + (rowbase + q0 + r) * HID + colbase + cv * 8;
                CP_ASYNC16(so + r * AP2 + cv * 16, g);
            }
        }
        CP_COMMIT();
    }

    float oacc[8][4];
#pragma unroll
    for (int j = 0; j < 8; ++j)
#pragma unroll
        for (int e = 0; e < 4; ++e) oacc[j][e] = 0.f;
    float den_r = 0.f, den_r8 = 0.f;

    // fragment address offsets
    const int qoff_row = (wid * 16 + (lane & 15)) * AP2;
    const int qoff_col = ((lane >> 4) * 8) * 2;
    const int koff_row = ((lane & 7) + (lane >> 4) * 8) * AP2;
    const int koff_col = (((lane >> 3) & 1) * 8) * 2;
    const int voff_row = ((lane & 15)) * AP2;
    const int voff_col = ((lane >> 4) * 8) * 2;

#pragma unroll 1
    for (int c = 0; c < 8; ++c) {
        const int k0 = c * 64;
        // ---- issue KV chunk copy ----
#pragma unroll
        for (int op = 0; op < 4; ++op) {
            const __nv_bfloat16* src = (op == 0) ? Kh : (op == 1) ? Kl : (op == 2) ? Vh : Vl;
            const uint32_t so = sb + SM_KH + op * (64 * AP2);
#pragma unroll
            for (int i = 0; i < 2; ++i) {
                const int u = i * 256 + tid;
                const int r = u >> 3, cv = u & 7;
                const void* g = src + (rowbase + k0 + r) * HID + colbase + cv * 8;
                CP_ASYNC16(so + r * AP2 + cv * 16, g);
            }
        }
        CP_COMMIT();
        if (tid < 64) msk01[tid] = (float)mask[b * TDIM + k0 + tid];
        CP_WAIT0();
        __syncthreads();

        // ---- S = Q K^T (3-term split), acc in sacc ----
        float sacc[8][4];
#pragma unroll
        for (int j = 0; j < 8; ++j)
#pragma unroll
            for (int e = 0; e < 4; ++e) sacc[j][e] = 0.f;

#pragma unroll
        for (int dk = 0; dk < 4; ++dk) {
            uint32_t ah[4], al[4];
            const uint32_t qa = sb + qoff_row + dk * 32 + qoff_col;
            ldm_x4(ah, qa + SM_QH);
            ldm_x4(al, qa + SM_QL);
#pragma unroll
            for (int kb = 0; kb < 4; ++kb) {
                uint32_t bh[4], bl[4];
                const uint32_t ka = sb + (kb * 16) * AP2 + koff_row + dk * 32 + koff_col;
                ldm_x4(bh, ka + SM_KH);
                ldm_x4(bl, ka + SM_KL);
                mma16816(sacc[2 * kb],     ah, &bh[0]);
                mma16816(sacc[2 * kb],     ah, &bl[0]);
                mma16816(sacc[2 * kb],     al, &bh[0]);
                mma16816(sacc[2 * kb + 1], ah, &bh[2]);
                mma16816(sacc[2 * kb + 1], ah, &bl[2]);
                mma16816(sacc[2 * kb + 1], al, &bh[2]);
            }
        }

        // ---- softmax (unnormalized): p = exp(mask/clip(s/8)) ----
        float dr = 0.f, dr8 = 0.f;
#pragma unroll
        for (int nt = 0; nt < 8; ++nt) {
            const int c0 = nt * 8 + (lane & 3) * 2;
            const float m0 = msk01[c0], m1 = msk01[c0 + 1];
#pragma unroll
            for (int e = 0; e < 4; ++e) {
                float s = sacc[nt][e] * 0.125f;
                s = fminf(fmaxf(s, -50.f), 50.f);
                s = ((e & 1) ? m1 : m0) * (s + 50.f) - 50.f;
                sacc[nt][e] = __expf(s);
            }
            dr  += sacc[nt][0] + sacc[nt][1];
            dr8 += sacc[nt][2] + sacc[nt][3];
        }
        dr  += __shfl_xor_sync(0xffffffff, dr, 1);
        dr  += __shfl_xor_sync(0xffffffff, dr, 2);
        dr8 += __shfl_xor_sync(0xffffffff, dr8, 1);
        dr8 += __shfl_xor_sync(0xffffffff, dr8, 2);
        den_r  += dr;
        den_r8 += dr8;

        // ---- PV: oacc += (Ph+Pl) @ (Vh+Vl), 3-term ----
#pragma unroll
        for (int kb = 0; kb < 4; ++kb) {
            uint32_t pah[4], pal[4];
            const int t0 = 2 * kb, t1 = 2 * kb + 1;
            pah[0] = pack_hi(sacc[t0][0], sacc[t0][1]);
            pah[1] = pack_hi(sacc[t0][2], sacc[t0][3]);
            pah[2] = pack_hi(sacc[t1][0], sacc[t1][1]);
            pah[3] = pack_hi(sacc[t1][2], sacc[t1][3]);
            pal[0] = pack_lo(sacc[t0][0], sacc[t0][1]);
            pal[1] = pack_lo(sacc[t0][2], sacc[t0][3]);
            pal[2] = pack_lo(sacc[t1][0], sacc[t1][1]);
            pal[3] = pack_lo(sacc[t1][2], sacc[t1][3]);
#pragma unroll
            for (int dnp = 0; dnp < 4; ++dnp) {
                uint32_t vh[4], vl[4];
                const uint32_t va = sb + (kb * 16) * AP2 + voff_row + dnp * 32 + voff_col;
                ldm_x4_t(vh, va + SM_VH);
                ldm_x4_t(vl, va + SM_VL);
                mma16816(oacc[2 * dnp],     pah, &vh[0]);
                mma16816(oacc[2 * dnp],     pah, &vl[0]);
                mma16816(oacc[2 * dnp],     pal, &vh[0]);
                mma16816(oacc[2 * dnp + 1], pah, &vh[2]);
                mma16816(oacc[2 * dnp + 1], pah, &vl[2]);
                mma16816(oacc[2 * dnp + 1], pal, &vh[2]);
            }
        }
        __syncthreads();   // done reading K/V/msk before next chunk copy
    }

    // ---- epilogue: normalize, write CTX hi/lo bf16 ----
    const float invr  = 1.f / den_r;
    const float invr8 = 1.f / den_r8;
    const size_t r0 = (rowbase + q0 + wid * 16 + (lane >> 2)) * HID + colbase;
    const size_t r8 = r0 + 8 * HID;
#pragma unroll
    for (int dn = 0; dn < 8; ++dn) {
        const int col = dn * 8 + (lane & 3) * 2;
        const float v0 = oacc[dn][0] * invr,  v1 = oacc[dn][1] * invr;
        const float v2 = oacc[dn][2] * invr8, v3 = oacc[dn][3] * invr8;
        *(uint32_t*)(Chi + r0 + col) = pack_hi(v0, v1);
        *(uint32_t*)(Clo + r0 + col) = pack_lo(v0, v1);
        *(uint32_t*)(Chi + r8 + col) = pack_hi(v2, v3);
        *(uint32_t*)(Clo + r8 + col) = pack_lo(v2, v3);
    }
}

// ---------------------------------------------------------------------------
// x [B, HID, T] fp32 -> transpose to [BT, HID] + split into bf16 hi/lo
// ---------------------------------------------------------------------------
__global__ void __launch_bounds__(256)
xpose_split_kernel(const float* __restrict__ x,
                   __nv_bfloat16* __restrict__ hi, __nv_bfloat16* __restrict__ lo)
{
    __shared__ float s[32][33];
    const int b = blockIdx.z, k0 = blockIdx.y * 32, t0 = blockIdx.x * 32;
    const int tx = threadIdx.x & 31, ty = threadIdx.x >> 5;
    const float* src = x + ((size_t)b * HID + k0) * TDIM + t0;
#pragma unroll
    for (int i = 0; i < 4; ++i)
        s[ty + 8 * i][tx] = src[(size_t)(ty + 8 * i) * TDIM + tx];
    __syncthreads();
#pragma unroll
    for (int i = 0; i < 4; ++i) {
        const int t = ty + 8 * i;
        const float v = s[tx][t];
        const __nv_bfloat16 hh = __float2bfloat16_rn(v);
        const __nv_bfloat16 ll = __float2bfloat16_rn(v - __bfloat162float(hh));
        const size_t o = (size_t)(b * TDIM + t0 + t) * HID + k0 + tx;
        hi[o] = hh;
        lo[o] = ll;
    }
}

__global__ void __launch_bounds__(256)
split_kernel(const float* __restrict__ src,
             __nv_bfloat16* __restrict__ hi, __nv_bfloat16* __restrict__ lo, int n4)
{
    const int i = blockIdx.x * 256 + threadIdx.x;
    if (i >= n4) return;
    const float4 v = ((const float4*)src)[i];
    uint2 hp, lp;
    hp.x = pack_hi(v.x, v.y); hp.y = pack_hi(v.z, v.w);
    lp.x = pack_lo(v.x, v.y); lp.y = pack_lo(v.z, v.w);
    ((uint2*)hi)[i] = hp;
    ((uint2*)lo)[i] = lp;
}

// ---------------------------------------------------------------------------
__global__ void __launch_bounds__(256)
maxreduce_kernel(const float* __restrict__ O, float* __restrict__ out)
{
    const int b = blockIdx.x;
    const int n = blockIdx.y * 256 + threadIdx.x;
    const float* p = O + (size_t)b * TDIM * HID + n;
    float m = -3.402823466e38f;
#pragma unroll 8
    for (int t = 0; t < TDIM; ++t) m = fmaxf(m, p[(size_t)t * HID]);
    out[b * HID + n] = m;
}

// ---------------------------------------------------------------------------
extern "C" void kernel_launch(void* const* d_in, const int* in_sizes, int n_in,
                              void* d_out, int out_size)
{
    const float* x    = (const float*)d_in[0];
    const int*   mask = (const int*)d_in[1];
    const float* W[4] = { (const float*)d_in[2], (const float*)d_in[4],
                          (const float*)d_in[6], (const float*)d_in[8] };
    const float* bq   = (const float*)d_in[3];
    const float* bk   = (const float*)d_in[5];
    const float* bv   = (const float*)d_in[7];
    const float* bo   = (const float*)d_in[9];
    float* out = (float*)d_out;

    float* O;
    __nv_bfloat16 *xhi, *xlo, *qhi, *qlo, *khi, *klo, *vhi, *vlo, *chi, *clo, *whi, *wlo;
    cudaGetSymbolAddress((void**)&O,   g_O);
    cudaGetSymbolAddress((void**)&xhi, g_xhi);
    cudaGetSymbolAddress((void**)&xlo, g_xlo);
    cudaGetSymbolAddress((void**)&qhi, g_qhi);
    cudaGetSymbolAddress((void**)&qlo, g_qlo);
    cudaGetSymbolAddress((void**)&khi, g_khi);
    cudaGetSymbolAddress((void**)&klo, g_klo);
    cudaGetSymbolAddress((void**)&vhi, g_vhi);
    cudaGetSymbolAddress((void**)&vlo, g_vlo);
    cudaGetSymbolAddress((void**)&chi, g_chi);
    cudaGetSymbolAddress((void**)&clo, g_clo);
    cudaGetSymbolAddress((void**)&whi, g_whi);
    cudaGetSymbolAddress((void**)&wlo, g_wlo);

    cudaFuncSetAttribute(gemm_mma_kernel<true>,  cudaFuncAttributeMaxDynamicSharedMemorySize,
                         GEMM_SMEM_BYTES);
    cudaFuncSetAttribute(gemm_mma_kernel<false>, cudaFuncAttributeMaxDynamicSharedMemorySize,
                         GEMM_SMEM_BYTES);
    cudaFuncSetAttribute(attn_mma_kernel, cudaFuncAttributeMaxDynamicSharedMemorySize,
                         ATTN_SMEM_BYTES);

    const int wn4 = HID * HID / 4;
    for (int i = 0; i < 4; ++i)
        split_kernel<<<(wn4 + 255) / 256, 256>>>(W[i], whi + (size_t)i * HID * HID,
                                                 wlo + (size_t)i * HID * HID, wn4);
    xpose_split_kernel<<<dim3(TDIM / 32, HID / 32, BDIM), 256>>>(x, xhi, xlo);

    const dim3 gg(HID / 128, BT / 128);
    const size_t WSZ = (size_t)HID * HID;

    gemm_mma_kernel<true><<<gg, 256, GEMM_SMEM_BYTES>>>(xhi, xlo, whi + 0 * WSZ, wlo + 0 * WSZ,
                                                        bq, nullptr, qhi, qlo);
    gemm_mma_kernel<true><<<gg, 256, GEMM_SMEM_BYTES>>>(xhi, xlo, whi + 1 * WSZ, wlo + 1 * WSZ,
                                                        bk, nullptr, khi, klo);
    gemm_mma_kernel<true><<<gg, 256, GEMM_SMEM_BYTES>>>(xhi, xlo, whi + 2 * WSZ, wlo + 2 * WSZ,
                                                        bv, nullptr, vhi, vlo);

    attn_mma_kernel<<<dim3(TDIM / 128, NH, BDIM), 256, ATTN_SMEM_BYTES>>>(
        qhi, qlo, khi, klo, vhi, vlo, mask, chi, clo);

    gemm_mma_kernel<false><<<gg, 256, GEMM_SMEM_BYTES>>>(chi, clo, whi + 3 * WSZ, wlo + 3 * WSZ,
                                                         bo, O, nullptr, nullptr);

    maxreduce_kernel<<<dim3(BDIM, HID / 256), 256>>>(O, out);
}